// round 3
// baseline (speedup 1.0000x reference)
#include <cuda_runtime.h>
#include <cstdint>

// ============================================================================
// out[b,n] = sum_k x[b,k] * W[k,n]
//   x: [512, 2^20] f32 row-major, W: [2^20, 128] f32 row-major, out: [512,128]
// Ampere-ISA path (PTX target is compute_103, no 'a' features):
//   cp.async 3-stage pipeline + mma.sync.m16n8k8.tf32, split-K 64, then reduce.
// W stages directly in native [K,N] layout (no transpose kernel needed).
// ============================================================================

static constexpr int M_TOTAL = 512;
static constexpr int N_DIM   = 128;
static constexpr int K_TOTAL = 1 << 20;

static constexpr int MTILE   = 128;
static constexpr int KTILE   = 32;
static constexpr int NUM_MT  = M_TOTAL / MTILE;    // 4
static constexpr int KSPLITS = 64;
static constexpr int K_CHUNK = K_TOTAL / KSPLITS;  // 16384
static constexpr int KITERS  = K_CHUNK / KTILE;    // 512
static constexpr int STAGES  = 3;

// SMEM pitches (floats), padded for conflict-free fragment loads:
//   A bank = (row*36 + c) % 32 = (4*g + c + const) -> bijective over warp
//   B bank = (k*136 + n) % 32  = (8*c + g + const) -> bijective over warp
static constexpr int A_PITCH = 36;
static constexpr int B_PITCH = 136;
static constexpr int A_SZ = MTILE * A_PITCH * 4;   // 18432 B
static constexpr int B_SZ = KTILE * B_PITCH * 4;   // 17408 B
static constexpr int STAGE_SZ = A_SZ + B_SZ;       // 35840 B
static constexpr int SMEM_BYTES = STAGES * STAGE_SZ; // 107520 B

// split-K partials scratch (device global = allowed scratch)
__device__ float g_part[(size_t)KSPLITS * NUM_MT * MTILE * N_DIM]; // 16 MiB

// ---------------------------------------------------------------------------
__device__ __forceinline__ uint32_t smem_to_u32(const void* p) {
    uint32_t a;
    asm("{ .reg .u64 t; cvta.to.shared.u64 t, %1; cvt.u32.u64 %0, t; }" : "=r"(a) : "l"(p));
    return a;
}

__device__ __forceinline__ void cp_async16(uint32_t dst, const void* src) {
    asm volatile("cp.async.cg.shared.global [%0], [%1], 16;" :: "r"(dst), "l"(src));
}
__device__ __forceinline__ void cp_commit() {
    asm volatile("cp.async.commit_group;" ::: "memory");
}
template <int N>
__device__ __forceinline__ void cp_wait() {
    asm volatile("cp.async.wait_group %0;" :: "n"(N) : "memory");
}

// mma.sync m16n8k8 tf32: operands are f32 bit patterns; HW uses tf32 bits.
__device__ __forceinline__ void mma_tf32(float* d, const uint32_t* a, const uint32_t* b) {
    asm volatile(
        "mma.sync.aligned.m16n8k8.row.col.f32.tf32.tf32.f32 "
        "{%0,%1,%2,%3}, {%4,%5,%6,%7}, {%8,%9}, {%0,%1,%2,%3};"
        : "+f"(d[0]), "+f"(d[1]), "+f"(d[2]), "+f"(d[3])
        : "r"(a[0]), "r"(a[1]), "r"(a[2]), "r"(a[3]), "r"(b[0]), "r"(b[1]));
}

// ---------------------------------------------------------------------------
// GEMM: grid = NUM_MT * KSPLITS (mt = bid & 3 so W-sharing CTAs are adjacent),
// 256 threads, warp grid 2(m) x 4(n): warp tile 64x32.
// ---------------------------------------------------------------------------
__global__ void __launch_bounds__(256, 2) gemm_kernel(
    const float* __restrict__ x, const float* __restrict__ W,
    float* __restrict__ partials) {
    extern __shared__ float smem[];
    const uint32_t sbase = smem_to_u32(smem);

    const int tid  = threadIdx.x;
    const int wid  = tid >> 5;
    const int lane = tid & 31;
    const int g = lane >> 2;     // groupID
    const int c = lane & 3;      // threadID_in_group
    const int m_off = (wid >> 2) * 64;  // warp m offset (0/64)
    const int n_off = (wid & 3) * 32;   // warp n offset (0..96)

    const int mt = blockIdx.x & (NUM_MT - 1);
    const int ks = blockIdx.x >> 2;
    const size_t m_base = (size_t)mt * MTILE;
    const size_t k0 = (size_t)ks * K_CHUNK;

    // ---- cp.async staging: 4 A-chunks + 4 B-chunks (16B) per thread ----
    auto copy_stage = [&](int s, int it) {
        const size_t kg = k0 + (size_t)it * KTILE;
        const uint32_t st = sbase + s * STAGE_SZ;
#pragma unroll
        for (int i = 0; i < 4; i++) {       // A: 128 rows x 128B
            int chunk = tid + i * 256;
            int row = chunk >> 3, q = chunk & 7;
            const float* src = x + (m_base + row) * K_TOTAL + kg + q * 4;
            cp_async16(st + row * (A_PITCH * 4) + q * 16, src);
        }
#pragma unroll
        for (int i = 0; i < 4; i++) {       // B: 32 rows x 512B (native [K,N])
            int chunk = tid + i * 256;
            int kr = chunk >> 5, nq = chunk & 31;
            const float* src = W + (kg + kr) * (size_t)N_DIM + nq * 4;
            cp_async16(st + A_SZ + kr * (B_PITCH * 4) + nq * 16, src);
        }
        cp_commit();
    };

    float acc[4][4][4];
#pragma unroll
    for (int mi = 0; mi < 4; mi++)
#pragma unroll
        for (int ni = 0; ni < 4; ni++)
#pragma unroll
            for (int r = 0; r < 4; r++) acc[mi][ni][r] = 0.0f;

    // prologue: prefetch 2 stages
    copy_stage(0, 0);
    copy_stage(1, 1);

    int s = 0;
    for (int it = 0; it < KITERS; it++) {
        cp_wait<1>();        // stage s data arrived (this thread's groups)
        __syncthreads();     // ...and everyone else's; also guards overwrite

        if (it + 2 < KITERS) {
            copy_stage((s + 2 >= STAGES) ? s + 2 - STAGES : s + 2, it + 2);
        } else {
            cp_commit();     // keep group counting uniform
        }

        const float* As = smem + (size_t)s * (STAGE_SZ / 4);
        const float* Bs = As + A_SZ / 4;
#pragma unroll
        for (int kk = 0; kk < 4; kk++) {
            const int kb = kk * 8;
            uint32_t a[4][4], b[4][2];
#pragma unroll
            for (int mi = 0; mi < 4; mi++) {
                int r0 = m_off + mi * 16 + g;
                a[mi][0] = __float_as_uint(As[r0 * A_PITCH + kb + c]);
                a[mi][1] = __float_as_uint(As[(r0 + 8) * A_PITCH + kb + c]);
                a[mi][2] = __float_as_uint(As[r0 * A_PITCH + kb + c + 4]);
                a[mi][3] = __float_as_uint(As[(r0 + 8) * A_PITCH + kb + c + 4]);
            }
#pragma unroll
            for (int ni = 0; ni < 4; ni++) {
                int col = n_off + ni * 8 + g;
                b[ni][0] = __float_as_uint(Bs[(kb + c) * B_PITCH + col]);
                b[ni][1] = __float_as_uint(Bs[(kb + c + 4) * B_PITCH + col]);
            }
#pragma unroll
            for (int mi = 0; mi < 4; mi++)
#pragma unroll
                for (int ni = 0; ni < 4; ni++)
                    mma_tf32(acc[mi][ni], a[mi], b[ni]);
        }
        if (++s == STAGES) s = 0;
    }

    // ---- epilogue: write 128x128 partial for this (ks, mt) ----
    float* pt = partials + (size_t)blockIdx.x * (MTILE * N_DIM);
#pragma unroll
    for (int mi = 0; mi < 4; mi++) {
        int r0 = m_off + mi * 16 + g;
#pragma unroll
        for (int ni = 0; ni < 4; ni++) {
            int col = n_off + ni * 8 + 2 * c;
            float2 lo = make_float2(acc[mi][ni][0], acc[mi][ni][1]);
            float2 hi = make_float2(acc[mi][ni][2], acc[mi][ni][3]);
            *reinterpret_cast<float2*>(pt + (size_t)r0 * N_DIM + col) = lo;
            *reinterpret_cast<float2*>(pt + (size_t)(r0 + 8) * N_DIM + col) = hi;
        }
    }
}

// ---------------------------------------------------------------------------
// Reduce 64 K-split partials -> out [512, 128]
// partial layout: [bid = ks*4 + mt][m][n]
// ---------------------------------------------------------------------------
__global__ void __launch_bounds__(256) reduce_kernel(const float* __restrict__ pt,
                                                     float* __restrict__ out) {
    int t = blockIdx.x * blockDim.x + threadIdx.x;   // 65536 threads
    int n  = t & (N_DIM - 1);
    int m  = (t >> 7) & (MTILE - 1);
    int mt = t >> 14;
    float s = 0.0f;
#pragma unroll 8
    for (int ks = 0; ks < KSPLITS; ks++)
        s += pt[(size_t)(ks * NUM_MT + mt) * (MTILE * N_DIM) + (size_t)m * N_DIM + n];
    out[(size_t)(mt * MTILE + m) * N_DIM + n] = s;
}

// ---------------------------------------------------------------------------
extern "C" void kernel_launch(void* const* d_in, const int* in_sizes, int n_in,
                              void* d_out, int out_size) {
    const float* x = (const float*)d_in[0];
    const float* W = (const float*)d_in[1];
    float* out = (float*)d_out;

    float* part = nullptr;
    cudaGetSymbolAddress((void**)&part, g_part);

    static bool attr_set = false;
    if (!attr_set) {
        cudaFuncSetAttribute(gemm_kernel, cudaFuncAttributeMaxDynamicSharedMemorySize,
                             SMEM_BYTES);
        attr_set = true;
    }

    gemm_kernel<<<NUM_MT * KSPLITS, 256, SMEM_BYTES>>>(x, W, part);
    reduce_kernel<<<(M_TOTAL * N_DIM) / 256, 256>>>(part, out);
}

// round 4
// speedup vs baseline: 1.2635x; 1.2635x over previous
#include <cuda_runtime.h>
#include <cstdint>
#include <cuda_fp16.h>

// ============================================================================
// out[b,n] = sum_k x[b,k] * W[k,n]
//   x: [512, 2^20] f32 row-major, W: [2^20, 128] f32, out: [512,128] f32
// fp16-MMA path: cp.async f32 staging -> in-SMEM cvt to packed half2 ->
// mma.sync.m16n8k16.f16 (f32 accum). Split-K 74 (grid 296 = one full wave
// at occ 2 on 148 SMs), partials reduced by a second kernel.
// ============================================================================

static constexpr int M_TOTAL = 512;
static constexpr int N_DIM   = 128;
static constexpr int K_TOTAL = 1 << 20;

static constexpr int MTILE   = 128;
static constexpr int KTILE   = 32;
static constexpr int NUM_MT  = M_TOTAL / MTILE;    // 4
static constexpr int KSPLITS = 74;                 // grid 296 = 148 SMs * occ 2
static constexpr int NTILES_K = K_TOTAL / KTILE;   // 32768 k-tiles
static constexpr int BASE_T  = NTILES_K / KSPLITS; // 442
static constexpr int REM_T   = NTILES_K - BASE_T * KSPLITS; // 60

// ---- SMEM layout (floats / u32) ----
// f32 A stage: 128 rows x pitch 36  (data 32)  = 4608 f
// f32 B stage: 32 rows  x pitch 128            = 4096 f
// stage = 8704 f, 2 stages = 17408 f
// fp16 A buf:  128 rows x pitch 20 u32 (data 16 u32 = 32 half) = 2560 u32
// fp16 B buf:  16 k2    x pitch 132 u32 (data 128)             = 2112 u32
static constexpr int A_PITCH_F = 36;
static constexpr int B_PITCH_F = 128;
static constexpr int F32_STAGE = MTILE * A_PITCH_F + KTILE * B_PITCH_F; // 8704
static constexpr int AH_PITCH  = 20;   // u32
static constexpr int BH_PITCH  = 132;  // u32
static constexpr int FP16_OFF  = 2 * F32_STAGE;                 // u32/f offset
static constexpr int AH_SIZE   = MTILE * AH_PITCH;              // 2560
static constexpr int SMEM_WORDS = FP16_OFF + AH_SIZE + 16 * BH_PITCH; // 22080
static constexpr int SMEM_BYTES = SMEM_WORDS * 4;               // 88320

// split-K partials scratch
__device__ float g_part[(size_t)KSPLITS * NUM_MT * MTILE * N_DIM]; // ~19.4 MiB

// ---------------------------------------------------------------------------
__device__ __forceinline__ uint32_t smem_to_u32(const void* p) {
    uint32_t a;
    asm("{ .reg .u64 t; cvta.to.shared.u64 t, %1; cvt.u32.u64 %0, t; }" : "=r"(a) : "l"(p));
    return a;
}
__device__ __forceinline__ void cp_async16(uint32_t dst, const void* src) {
    asm volatile("cp.async.cg.shared.global [%0], [%1], 16;" :: "r"(dst), "l"(src));
}
__device__ __forceinline__ void cp_commit() {
    asm volatile("cp.async.commit_group;" ::: "memory");
}
template <int N>
__device__ __forceinline__ void cp_wait() {
    asm volatile("cp.async.wait_group %0;" :: "n"(N) : "memory");
}
__device__ __forceinline__ uint32_t pack_h2(float lo, float hi) {
    __half2 h = __floats2half2_rn(lo, hi);   // .x = lo (low 16 bits)
    return *reinterpret_cast<uint32_t*>(&h);
}
// m16n8k16 fp16 mma, f32 accumulate
__device__ __forceinline__ void mma_f16(float* d, const uint32_t* a, const uint32_t* b) {
    asm volatile(
        "mma.sync.aligned.m16n8k16.row.col.f32.f16.f16.f32 "
        "{%0,%1,%2,%3}, {%4,%5,%6,%7}, {%8,%9}, {%0,%1,%2,%3};"
        : "+f"(d[0]), "+f"(d[1]), "+f"(d[2]), "+f"(d[3])
        : "r"(a[0]), "r"(a[1]), "r"(a[2]), "r"(a[3]), "r"(b[0]), "r"(b[1]));
}

// ---------------------------------------------------------------------------
// GEMM: grid 296 (mt = bid&3, ks = bid>>2), 256 threads, warps 2(m) x 4(n),
// warp tile 64x32, KTILE=32 per stage (2 x k16 mma steps).
// ---------------------------------------------------------------------------
__global__ void __launch_bounds__(256, 2) gemm_kernel(
    const float* __restrict__ x, const float* __restrict__ W,
    float* __restrict__ partials) {
    extern __shared__ float smem[];
    const uint32_t sbase = smem_to_u32(smem);

    const int tid  = threadIdx.x;
    const int wid  = tid >> 5;
    const int lane = tid & 31;
    const int g = lane >> 2;            // groupID (row/col within frag)
    const int c = lane & 3;             // threadID_in_group
    const int m_off = (wid >> 2) * 64;  // warp m offset
    const int n_off = (wid & 3) * 32;   // warp n offset

    const int mt = blockIdx.x & (NUM_MT - 1);
    const int ks = blockIdx.x >> 2;
    const size_t m_base = (size_t)mt * MTILE;
    const int nt = BASE_T + (ks < REM_T ? 1 : 0);                 // my k-tiles
    const long t0 = (long)ks * BASE_T + (ks < REM_T ? ks : REM_T); // first tile

    // ---- producer: stage f32 tile `tile` into f32 stage p ----
    auto copy_stage = [&](int p, int tile) {
        const size_t kg = (size_t)(t0 + tile) * KTILE;
        const uint32_t st = sbase + p * (F32_STAGE * 4);
#pragma unroll
        for (int i = 0; i < 4; i++) {          // A: 128 rows x 128B
            int ch = tid + i * 256;
            int row = ch >> 3, q = ch & 7;
            const float* src = x + (m_base + row) * K_TOTAL + kg + q * 4;
            cp_async16(st + row * (A_PITCH_F * 4) + q * 16, src);
        }
#pragma unroll
        for (int i = 0; i < 4; i++) {          // B: 32 rows x 512B, native [K,N]
            int ch = tid + i * 256;
            int kr = ch >> 5, nq = ch & 31;
            const float* src = W + (kg + kr) * (size_t)N_DIM + nq * 4;
            cp_async16(st + (MTILE * A_PITCH_F + kr * B_PITCH_F) * 4 + nq * 16, src);
        }
        cp_commit();
    };

    float acc[4][4][4];
#pragma unroll
    for (int mi = 0; mi < 4; mi++)
#pragma unroll
        for (int ni = 0; ni < 4; ni++)
#pragma unroll
            for (int r = 0; r < 4; r++) acc[mi][ni][r] = 0.0f;

    uint32_t* const Ah = reinterpret_cast<uint32_t*>(smem + FP16_OFF);
    uint32_t* const Bh = Ah + AH_SIZE;

    copy_stage(0, 0);
    copy_stage(1, 1);

    const int cv_row = tid >> 1, cv_h = tid & 1;   // A-convert assignment
    const int cv_k2b = tid >> 5, cv_n0 = (tid & 31) * 4;

    for (int it = 0; it < nt; it++) {
        const int p = it & 1;
        cp_wait<1>();
        __syncthreads();   // f32[p] visible to all; fp16 bufs free (mma done)

        // ---- convert f32[p] -> packed half2 buffers ----
        {
            const float* Af = smem + p * F32_STAGE;
            const float* Bf = Af + MTILE * A_PITCH_F;
            // A: thread -> (row, half): 16 f32 -> 8 u32
            const float4* asrc = reinterpret_cast<const float4*>(Af + cv_row * A_PITCH_F + cv_h * 16);
            uint32_t* adst = Ah + cv_row * AH_PITCH + cv_h * 8;
#pragma unroll
            for (int i = 0; i < 4; i++) {
                float4 v = asrc[i];
                adst[2 * i]     = pack_h2(v.x, v.y);
                adst[2 * i + 1] = pack_h2(v.z, v.w);
            }
            // B: pack k-pairs: Bh[k2][n] = {B[2k2][n], B[2k2+1][n]}
#pragma unroll
            for (int i = 0; i < 2; i++) {
                int k2 = cv_k2b + 8 * i;
                const float4 lo = *reinterpret_cast<const float4*>(Bf + (2 * k2) * B_PITCH_F + cv_n0);
                const float4 hi = *reinterpret_cast<const float4*>(Bf + (2 * k2 + 1) * B_PITCH_F + cv_n0);
                uint4 o;
                o.x = pack_h2(lo.x, hi.x);
                o.y = pack_h2(lo.y, hi.y);
                o.z = pack_h2(lo.z, hi.z);
                o.w = pack_h2(lo.w, hi.w);
                *reinterpret_cast<uint4*>(Bh + k2 * BH_PITCH + cv_n0) = o;
            }
        }
        __syncthreads();   // fp16 bufs complete; f32[p] fully consumed

        if (it + 2 < nt) copy_stage(p, it + 2);
        else cp_commit();  // keep group counting uniform

        // ---- 2 x k16 mma steps ----
#pragma unroll
        for (int kk = 0; kk < 2; kk++) {
            uint32_t a[4][4], b[4][2];
#pragma unroll
            for (int mi = 0; mi < 4; mi++) {
                const int r0 = m_off + mi * 16 + g;
                const uint32_t* A0 = Ah + r0 * AH_PITCH + kk * 8;
                const uint32_t* A1 = Ah + (r0 + 8) * AH_PITCH + kk * 8;
                a[mi][0] = A0[c];
                a[mi][1] = A1[c];
                a[mi][2] = A0[c + 4];
                a[mi][3] = A1[c + 4];
            }
#pragma unroll
            for (int ni = 0; ni < 4; ni++) {
                const int col = n_off + ni * 8 + g;
                b[ni][0] = Bh[(kk * 8 + c) * BH_PITCH + col];
                b[ni][1] = Bh[(kk * 8 + c + 4) * BH_PITCH + col];
            }
#pragma unroll
            for (int mi = 0; mi < 4; mi++)
#pragma unroll
                for (int ni = 0; ni < 4; ni++)
                    mma_f16(acc[mi][ni], a[mi], b[ni]);
        }
    }

    // ---- epilogue: write 128x128 partial for this (ks, mt) ----
    float* pt = partials + (size_t)blockIdx.x * (MTILE * N_DIM);
#pragma unroll
    for (int mi = 0; mi < 4; mi++) {
        int r0 = m_off + mi * 16 + g;
#pragma unroll
        for (int ni = 0; ni < 4; ni++) {
            int col = n_off + ni * 8 + 2 * c;
            float2 lo = make_float2(acc[mi][ni][0], acc[mi][ni][1]);
            float2 hi = make_float2(acc[mi][ni][2], acc[mi][ni][3]);
            *reinterpret_cast<float2*>(pt + (size_t)r0 * N_DIM + col) = lo;
            *reinterpret_cast<float2*>(pt + (size_t)(r0 + 8) * N_DIM + col) = hi;
        }
    }
}

// ---------------------------------------------------------------------------
// Reduce 74 K-split partials -> out [512, 128]
// ---------------------------------------------------------------------------
__global__ void __launch_bounds__(256) reduce_kernel(const float* __restrict__ pt,
                                                     float* __restrict__ out) {
    int t = blockIdx.x * blockDim.x + threadIdx.x;   // 65536 threads
    int n  = t & (N_DIM - 1);
    int m  = (t >> 7) & (MTILE - 1);
    int mt = t >> 14;
    float s = 0.0f;
#pragma unroll 2
    for (int ks = 0; ks < KSPLITS; ks++)
        s += pt[(size_t)(ks * NUM_MT + mt) * (MTILE * N_DIM) + (size_t)m * N_DIM + n];
    out[(size_t)(mt * MTILE + m) * N_DIM + n] = s;
}

// ---------------------------------------------------------------------------
extern "C" void kernel_launch(void* const* d_in, const int* in_sizes, int n_in,
                              void* d_out, int out_size) {
    const float* x = (const float*)d_in[0];
    const float* W = (const float*)d_in[1];
    float* out = (float*)d_out;

    float* part = nullptr;
    cudaGetSymbolAddress((void**)&part, g_part);

    static bool attr_set = false;
    if (!attr_set) {
        cudaFuncSetAttribute(gemm_kernel, cudaFuncAttributeMaxDynamicSharedMemorySize,
                             SMEM_BYTES);
        attr_set = true;
    }

    gemm_kernel<<<NUM_MT * KSPLITS, 256, SMEM_BYTES>>>(x, W, part);
    reduce_kernel<<<(M_TOTAL * N_DIM) / 256, 256>>>(part, out);
}